// round 12
// baseline (speedup 1.0000x reference)
#include <cuda_runtime.h>
#include <cstdint>

#define HH 448
#define WW 512
#define HW (HH*WW)        // 229376
#define CHW 65536         // per-h plane: 128*512 ([c][w]) or 512*128 ([w][c])

typedef unsigned long long ull;

// scratch (allocation-free rule)
__device__ float g_t1[(size_t)HH*CHW];      // [h][c][w]
__device__ float g_xr[(size_t)HH*CHW];      // TRANSPOSED: [h][w][c]
__device__ int   g_inds[HW];

__device__ __forceinline__ ull pk2(float v){
    ull r; unsigned u = __float_as_uint(v);
    asm("mov.b64 %0, {%1, %1};" : "=l"(r) : "r"(u));
    return r;
}
__device__ __forceinline__ void fma2(ull& d, ull a, ull b){
    asm("fma.rn.f32x2 %0, %1, %2, %0;" : "+l"(d) : "l"(a), "l"(b));
}
__device__ __forceinline__ float2 up2(ull v){
    unsigned lo, hi;
    asm("mov.b64 {%0, %1}, %2;" : "=r"(lo), "=r"(hi) : "l"(v));
    return make_float2(__uint_as_float(lo), __uint_as_float(hi));
}
__device__ __forceinline__ float lrelu(float v){ return v >= 0.f ? v : 0.01f*v; }

// ---- shared layout (floats) ----
// Xr  [128c][128w] @0      (16384) -- resident activation tile
// WsB [2][16][128] @16384  (4096)  -- W double buffer (reused for argmax red.)
// aux @20480: wsm(128) + biasD(129)
#define SM_X 0
#define SM_W 16384
#define SM_AUX 20480
#define SM_FLOATS (20480 + 260)

// One GEMM stage vs a RESIDENT X tile: acc[8o][4 pairs] += W(128x128) * Xr.
// Only W is streamed (8 chunks of 16 k, double-buffered, XOR swizzle).
// If MASK: threads tid<128 also accumulate the 129th classifier row
// (mAcc partials, col = tid) from Xr.
template<bool MASK>
__device__ __forceinline__ void stage_res(
    const float* __restrict__ Wg, const float* __restrict__ Xr,
    float* __restrict__ WsB, ull (&acc)[8][4],
    const float* __restrict__ wsm, float* __restrict__ mAcc)
{
    const int tid = threadIdx.x;
    const int og = tid >> 4, wg = tid & 15;
    const int o0 = og << 3, t4 = wg << 2;
    const int wq = tid & 3, wo = tid >> 2;

    float4 wst0, wst1;
    wst0 = *reinterpret_cast<const float4*>(Wg + wo*128 + wq*4);
    wst1 = *reinterpret_cast<const float4*>(Wg + (wo+64)*128 + wq*4);
    {
        const float* s0 = &wst0.x; const float* s1 = &wst1.x;
        #pragma unroll
        for (int i = 0; i < 4; ++i){
            int k = wq*4 + i;
            WsB[k*128 + (wo ^ (wq<<3))] = s0[i];         // conflict-free STS
            WsB[k*128 + ((wo+64) ^ (wq<<3))] = s1[i];
        }
    }
    __syncthreads();

    int buf = 0;
    #pragma unroll 1
    for (int ch = 0; ch < 8; ++ch){
        if (ch < 7){
            int k0 = (ch+1)*16;
            wst0 = *reinterpret_cast<const float4*>(Wg + wo*128 + k0 + wq*4);
            wst1 = *reinterpret_cast<const float4*>(Wg + (wo+64)*128 + k0 + wq*4);
        }
        const float* Wb = WsB + buf*2048;
        const float* Xc = Xr + ch*2048;
        #pragma unroll
        for (int k = 0; k < 16; ++k){
            int wOff = ((k >> 2) & 3) << 3;
            const float4* wr = reinterpret_cast<const float4*>(&Wb[k*128 + (o0 ^ wOff)]);
            float4 wa = wr[0], wb2 = wr[1];
            float wv[8] = {wa.x,wa.y,wa.z,wa.w,wb2.x,wb2.y,wb2.z,wb2.w};
            ulonglong2 v0 = *reinterpret_cast<const ulonglong2*>(&Xc[k*128 + t4]);
            ulonglong2 v1 = *reinterpret_cast<const ulonglong2*>(&Xc[k*128 + t4 + 64]);
            #pragma unroll
            for (int o = 0; o < 8; ++o){
                ull wp = pk2(wv[o]);
                fma2(acc[o][0], v0.x, wp);
                fma2(acc[o][1], v0.y, wp);
                fma2(acc[o][2], v1.x, wp);
                fma2(acc[o][3], v1.y, wp);
            }
        }
        if (MASK && tid < 128){
            #pragma unroll
            for (int k = 0; k < 16; k += 2){
                mAcc[0] = fmaf(Xc[k*128 + tid],     wsm[ch*16 + k],     mAcc[0]);
                mAcc[1] = fmaf(Xc[(k+1)*128 + tid], wsm[ch*16 + k + 1], mAcc[1]);
            }
        }
        if (ch < 7){
            int nb = buf ^ 1;
            float* d = WsB + nb*2048;
            const float* s0 = &wst0.x; const float* s1 = &wst1.x;
            #pragma unroll
            for (int i = 0; i < 4; ++i){
                int k = wq*4 + i;
                d[k*128 + (wo ^ (wq<<3))] = s0[i];
                d[k*128 + ((wo+64) ^ (wq<<3))] = s1[i];
            }
            __syncthreads();
            buf = nb;
        }
    }
}

#define ZERO_ACC(acc) do { _Pragma("unroll") for(int o=0;o<8;o++){ _Pragma("unroll") for(int q=0;q<4;q++) (acc)[o][q]=0ull; } } while(0)

// Fused L1: load X tile once (resident) -> reg1 -> xr [h][w][c];
// cl1 -> t1 [h][c][w]. X read from DRAM exactly once.
__global__ void __launch_bounds__(256, 2)
kA(const float* __restrict__ x_in,
   const float* __restrict__ w_cl1, const float* __restrict__ b_cl1,
   const float* __restrict__ w_reg1, const float* __restrict__ b_reg1,
   float* __restrict__ t1, float* __restrict__ xr)
{
    extern __shared__ float sm[];
    float* Xr  = sm + SM_X;
    float* WsB = sm + SM_W;

    const int tid = threadIdx.x;
    const int h = blockIdx.y, wBase = blockIdx.x * 128;
    const int og = tid >> 4, wg = tid & 15;
    const int o0 = og << 3, t4 = wg << 2;

    // load X tile resident: x_in[c][h][w]
    {
        const float* xs = x_in + (size_t)h*WW + wBase;
        #pragma unroll 4
        for (int i = tid; i < 4096; i += 256){
            int c = i >> 5, f = i & 31;
            *reinterpret_cast<float4*>(&Xr[c*128 + f*4]) =
                *reinterpret_cast<const float4*>(xs + (size_t)c*HW + f*4);
        }
    }
    // ordered by stage_res prologue __syncthreads

    ull acc[8][4];
    float mDummy[2];

    // ---- reg1 -> xr (transposed [h][w][c]) ----
    ZERO_ACC(acc);
    stage_res<false>(w_reg1 + (size_t)h*16384, Xr, WsB, acc, nullptr, mDummy);
    #pragma unroll
    for (int half = 0; half < 2; ++half){
        #pragma unroll
        for (int i = 0; i < 4; ++i){
            int w = wBase + t4 + i + half*64;
            float vv[8];
            #pragma unroll
            for (int o = 0; o < 8; ++o){
                float2 f2 = up2(acc[o][half*2 + (i>>1)]);
                vv[o] = lrelu(((i & 1) ? f2.y : f2.x) + b_reg1[h*128 + o0 + o]);
            }
            float* dst = xr + (size_t)h*CHW + (size_t)w*128 + o0;
            *reinterpret_cast<float4*>(dst)     = make_float4(vv[0],vv[1],vv[2],vv[3]);
            *reinterpret_cast<float4*>(dst + 4) = make_float4(vv[4],vv[5],vv[6],vv[7]);
        }
    }

    // ---- cl1 -> t1 ([h][c][w]) ----
    ZERO_ACC(acc);
    stage_res<false>(w_cl1 + (size_t)h*16384, Xr, WsB, acc, nullptr, mDummy);
    #pragma unroll
    for (int o = 0; o < 8; ++o){
        float bo = b_cl1[h*128 + o0 + o];
        float* yo = t1 + (size_t)h*CHW + (size_t)(o0+o)*WW + wBase;
        float2 a0 = up2(acc[o][0]), a1 = up2(acc[o][1]);
        float2 a2 = up2(acc[o][2]), a3 = up2(acc[o][3]);
        *reinterpret_cast<float4*>(yo + t4) =
            make_float4(lrelu(a0.x+bo), lrelu(a0.y+bo), lrelu(a1.x+bo), lrelu(a1.y+bo));
        *reinterpret_cast<float4*>(yo + t4 + 64) =
            make_float4(lrelu(a2.x+bo), lrelu(a2.y+bo), lrelu(a3.x+bo), lrelu(a3.y+bo));
    }
}

// Fused L2+L3: load t1 tile resident -> cl2 -> overwrite in place (t2) ->
// cl3 + mask + in-CTA argmax. t2 never touches DRAM; logits stay on-chip.
__global__ void __launch_bounds__(256, 2)
kB(const float* __restrict__ t1,
   const float* __restrict__ w_cl2, const float* __restrict__ b_cl2,
   const float* __restrict__ w_cl3, const float* __restrict__ b_cl3,
   int* __restrict__ inds, float* __restrict__ outMask)
{
    extern __shared__ float sm[];
    float* Xr   = sm + SM_X;
    float* WsB  = sm + SM_W;
    float* wsm  = sm + SM_AUX;          // 128
    float* biasD = sm + SM_AUX + 128;   // 129

    const int tid = threadIdx.x;
    const int h = blockIdx.y, wBase = blockIdx.x * 128;
    const int og = tid >> 4, wg = tid & 15;
    const int o0 = og << 3, t4 = wg << 2;

    // load t1 tile resident ([c][w] rows)
    {
        const float* xs = t1 + (size_t)h*CHW + wBase;
        #pragma unroll 4
        for (int i = tid; i < 4096; i += 256){
            int c = i >> 5, f = i & 31;
            *reinterpret_cast<float4*>(&Xr[c*128 + f*4]) =
                *reinterpret_cast<const float4*>(xs + (size_t)c*WW + f*4);
        }
    }
    if (tid < 128){
        wsm[tid] = w_cl3[(size_t)h*16512 + 128*128 + tid];
        biasD[tid] = b_cl3[h*129 + tid];
    }
    if (tid == 128) biasD[128] = b_cl3[h*129 + 128];

    ull acc[8][4];
    float mAcc[2] = {0.f, 0.f};
    float mDummy[2];

    // ---- cl2: Xr -> Xr in place ----
    ZERO_ACC(acc);
    stage_res<false>(w_cl2 + (size_t)h*16384, Xr, WsB, acc, nullptr, mDummy);
    __syncthreads();                 // all reads of old Xr done before overwrite
    #pragma unroll
    for (int o = 0; o < 8; ++o){
        float bo = b_cl2[h*128 + o0 + o];
        float2 a0 = up2(acc[o][0]), a1 = up2(acc[o][1]);
        float2 a2 = up2(acc[o][2]), a3 = up2(acc[o][3]);
        *reinterpret_cast<float4*>(&Xr[(o0+o)*128 + t4]) =
            make_float4(lrelu(a0.x+bo), lrelu(a0.y+bo), lrelu(a1.x+bo), lrelu(a1.y+bo));
        *reinterpret_cast<float4*>(&Xr[(o0+o)*128 + t4 + 64]) =
            make_float4(lrelu(a2.x+bo), lrelu(a2.y+bo), lrelu(a3.x+bo), lrelu(a3.y+bo));
    }
    // next stage's prologue __syncthreads orders writes before reads

    // ---- cl3 + mask: Xr(t2) -> argmax ----
    ZERO_ACC(acc);
    stage_res<true>(w_cl3 + (size_t)h*16512, Xr, WsB, acc, wsm, mAcc);

    // per-thread argmax over its 8 classes for its 8 w (ascending class order,
    // strict > keeps the first max like jnp.argmax)
    float bestv[8]; int besti[8];
    #pragma unroll
    for (int o = 0; o < 8; ++o){
        float bo = biasD[o0 + o];
        float2 p0 = up2(acc[o][0]), p1 = up2(acc[o][1]);
        float2 p2 = up2(acc[o][2]), p3 = up2(acc[o][3]);
        float vals[8] = {p0.x+bo, p0.y+bo, p1.x+bo, p1.y+bo,
                         p2.x+bo, p2.y+bo, p3.x+bo, p3.y+bo};
        #pragma unroll
        for (int j = 0; j < 8; ++j){
            if (o == 0){ bestv[j] = vals[j]; besti[j] = o0; }
            else if (vals[j] > bestv[j]){ bestv[j] = vals[j]; besti[j] = o0 + o; }
        }
    }
    __syncthreads();    // all FMA reads of WsB done; reuse it for the reduction
    float* rv = WsB;                                  // [16 og][128 w]
    int*   ri = reinterpret_cast<int*>(WsB + 2048);   // [16 og][128 w]
    #pragma unroll
    for (int j = 0; j < 8; ++j){
        int w = (j < 4) ? (t4 + j) : (64 + t4 + j - 4);
        rv[og*128 + w] = bestv[j];
        ri[og*128 + w] = besti[j];
    }
    __syncthreads();
    if (tid < 128){
        float bv = rv[tid]; int bi = ri[tid];
        #pragma unroll
        for (int g = 1; g < 16; ++g){     // ascending class blocks: first max wins
            float v = rv[g*128 + tid];
            if (v > bv){ bv = v; bi = ri[g*128 + tid]; }
        }
        const int pg = h*WW + wBase + tid;
        inds[pg] = bi;
        outMask[pg] = lrelu(mAcc[0] + mAcc[1] + biasD[128]);
    }
}

// Final: gathered per-pixel 128->4->1 regressor, warp-cooperative,
// TWO pixels in flight per iteration (independent FMA/shuffle chains).
// Reproduces the reference's index scramble: rows use n = w*448 + h, while
// inds_r interprets the same flat n as (h2, w2i) on a (448,512) grid.
__global__ void __launch_bounds__(256)
k_final(const float* __restrict__ xrT, const int* __restrict__ inds,
        const float* __restrict__ w2, const float* __restrict__ b2,
        const float* __restrict__ w3, const float* __restrict__ b3,
        float* __restrict__ out)
{
    const int warp = (blockIdx.x * blockDim.x + threadIdx.x) >> 5;
    const int lane = threadIdx.x & 31;
    const int base = warp * 32;
    if (base >= HW) return;

    float res = 0.f;
    #pragma unroll 1
    for (int it = 0; it < 16; ++it){
        const int p0 = base + 2*it, p1 = p0 + 1;
        const int h = p0 >> 9, w0 = p0 & 511;
        const int n0 = w0*HH + h, n1 = n0 + HH;
        const int j0 = (n0 >> 9)*128 + __ldg(&inds[n0]);
        const int j1 = (n1 >> 9)*128 + __ldg(&inds[n1]);

        const float4* wpA = reinterpret_cast<const float4*>(w2 + (size_t)j0*512);
        const float4* wpB = reinterpret_cast<const float4*>(w2 + (size_t)j1*512);
        const float*  xpA = xrT + (size_t)h*CHW + (size_t)w0*128;
        const float*  xpB = xpA + 128;

        float4 a = make_float4(0.f,0.f,0.f,0.f);
        float4 b = make_float4(0.f,0.f,0.f,0.f);
        #pragma unroll
        for (int r = 0; r < 4; ++r){
            int c = r*32 + lane;
            float  xa = __ldg(&xpA[c]);
            float  xb = __ldg(&xpB[c]);
            float4 wa = __ldg(&wpA[c]);
            float4 wb = __ldg(&wpB[c]);
            a.x = fmaf(xa, wa.x, a.x); b.x = fmaf(xb, wb.x, b.x);
            a.y = fmaf(xa, wa.y, a.y); b.y = fmaf(xb, wb.y, b.y);
            a.z = fmaf(xa, wa.z, a.z); b.z = fmaf(xb, wb.z, b.z);
            a.w = fmaf(xa, wa.w, a.w); b.w = fmaf(xb, wb.w, b.w);
        }
        #pragma unroll
        for (int s = 16; s > 0; s >>= 1){
            a.x += __shfl_xor_sync(0xffffffffu, a.x, s);
            b.x += __shfl_xor_sync(0xffffffffu, b.x, s);
            a.y += __shfl_xor_sync(0xffffffffu, a.y, s);
            b.y += __shfl_xor_sync(0xffffffffu, b.y, s);
            a.z += __shfl_xor_sync(0xffffffffu, a.z, s);
            b.z += __shfl_xor_sync(0xffffffffu, b.z, s);
            a.w += __shfl_xor_sync(0xffffffffu, a.w, s);
            b.w += __shfl_xor_sync(0xffffffffu, b.w, s);
        }
        if (lane == 2*it || lane == 2*it + 1){
            const bool odd = (lane & 1);
            const int  j   = odd ? j1 : j0;
            const float4 v = odd ? b : a;
            float4 bb  = *reinterpret_cast<const float4*>(b2 + 4*(size_t)j);
            float h0 = lrelu(v.x + bb.x), h1 = lrelu(v.y + bb.y);
            float h2 = lrelu(v.z + bb.z), h3 = lrelu(v.w + bb.w);
            float4 w3v = *reinterpret_cast<const float4*>(w3 + 4*(size_t)j);
            float r2 = b3[j];
            r2 = fmaf(h0, w3v.x, r2); r2 = fmaf(h1, w3v.y, r2);
            r2 = fmaf(h2, w3v.z, r2); r2 = fmaf(h3, w3v.w, r2);
            res = ((float)__ldg(&inds[base + lane]) + r2) * (1.0f/128.0f);
        }
    }
    out[base + lane] = res;   // coalesced store of the warp's 32 results
}

extern "C" void kernel_launch(void* const* d_in, const int* in_sizes, int n_in,
                              void* d_out, int out_size)
{
    (void)in_sizes; (void)n_in; (void)out_size;
    const float* x_in  = (const float*)d_in[0];
    const float* w_cl1 = (const float*)d_in[1];
    const float* b_cl1 = (const float*)d_in[2];
    const float* w_cl2 = (const float*)d_in[3];
    const float* b_cl2 = (const float*)d_in[4];
    const float* w_cl3 = (const float*)d_in[5];
    const float* b_cl3 = (const float*)d_in[6];
    const float* w_reg1= (const float*)d_in[7];
    const float* b_reg1= (const float*)d_in[8];
    const float* w2    = (const float*)d_in[9];
    const float* b2    = (const float*)d_in[10];
    const float* w3    = (const float*)d_in[11];
    const float* b3    = (const float*)d_in[12];
    float* out = (float*)d_out;

    float *t1, *xr; int* inds;
    cudaGetSymbolAddress((void**)&t1, g_t1);
    cudaGetSymbolAddress((void**)&xr, g_xr);
    cudaGetSymbolAddress((void**)&inds, g_inds);

    const int smemB = SM_FLOATS * 4;   // ~83KB -> 2 CTAs/SM
    cudaFuncSetAttribute(kA, cudaFuncAttributeMaxDynamicSharedMemorySize, smemB);
    cudaFuncSetAttribute(kB, cudaFuncAttributeMaxDynamicSharedMemorySize, smemB);

    // L1 fused: x -> (xr, t1); X read once
    kA<<<dim3(4, HH), 256, smemB>>>(x_in, w_cl1, b_cl1, w_reg1, b_reg1, t1, xr);
    // L2+L3 fused: t1 -> inds + mask (t2 and logits stay on-chip)
    kB<<<dim3(4, HH), 256, smemB>>>(t1, w_cl2, b_cl2, w_cl3, b_cl3, inds, out + HW);
    // regressor -> out[0:HW)
    k_final<<<HW/32/8, 256>>>(xr, inds, w2, b2, w3, b3, out);
}